// round 2
// baseline (speedup 1.0000x reference)
#include <cuda_runtime.h>

// ---------------- problem capacity constants ----------------
#define NN_CAP 100000
#define EE_CAP 1600000
#define ET_CAP (EE_CAP + NN_CAP)

// ---------------- scratch (device globals; no mallocs allowed) ----------------
__device__ float    g_xl1[(size_t)NN_CAP * 128];
__device__ float    g_xr1[(size_t)NN_CAP * 128];
__device__ float    g_h  [(size_t)NN_CAP * 128];
__device__ float    g_agg1[(size_t)NN_CAP * 128];
__device__ float    g_score1[(size_t)ET_CAP * 8];
__device__ unsigned g_mx1[(size_t)NN_CAP * 8];
__device__ float    g_den1[(size_t)NN_CAP * 8];
__device__ float    g_xl2[(size_t)NN_CAP * 64];
__device__ float    g_xr2[(size_t)NN_CAP * 64];
__device__ float    g_score2[(size_t)ET_CAP];
__device__ unsigned g_mx2[NN_CAP];
__device__ float    g_den2[NN_CAP];
__device__ int      g_is64;   // 1 if edge_index buffer is int64, 0 if int32

// ---------------- helpers ----------------
__device__ __forceinline__ unsigned enc_f(float f) {
    unsigned u = __float_as_uint(f);
    return (u >> 31) ? ~u : (u | 0x80000000u);
}
__device__ __forceinline__ float dec_f(unsigned e) {
    return (e >> 31) ? __uint_as_float(e ^ 0x80000000u) : __uint_as_float(~e);
}
__device__ __forceinline__ float lrelu(float v) { return v > 0.f ? v : 0.2f * v; }

// fetch (src,dst) for edge e, robust to int32 vs int64 storage
__device__ __forceinline__ void edge_sd(const int* __restrict__ ei, int e, int E,
                                        int is64, int& s, int& d) {
    if (is64) { s = ei[2 * e]; d = ei[2 * (E + e)]; }
    else      { s = ei[e];     d = ei[E + e]; }
}

// ---------------- dtype detection: int64 values < 2^31 have zero odd slots ----------------
__global__ void k_detect(const int* __restrict__ ei, int E) {
    __shared__ int nz;
    if (threadIdx.x == 0) nz = 0;
    __syncthreads();
    int cnt = E < 4096 ? E : 4096;
    for (int i = threadIdx.x; i < cnt; i += blockDim.x)
        if (ei[2 * i + 1] != 0) nz = 1;
    __syncthreads();
    if (threadIdx.x == 0) g_is64 = (nz == 0) ? 1 : 0;
}

// ---------------- init: zero everything that accumulates ----------------
__global__ void k_init(float* __restrict__ dout, int N) {
    int t = blockIdx.x * blockDim.x + threadIdx.x;
    if (t < N * 128) g_agg1[t] = 0.f;
    if (t < N * 8)  { g_mx1[t] = 0u; g_den1[t] = 0.f; }
    if (t < N)      { g_mx2[t] = 0u; g_den2[t] = 0.f; }
    if (t < N * 64) dout[t] = 0.f;
}

// ---------------- GEMM: Y[N,NOUT] = X[N,128] @ W[128,NOUT] + B ----------------
template <int NOUT>
__global__ void k_gemm(const float* __restrict__ X, const float* __restrict__ W,
                       const float* __restrict__ B, float* __restrict__ Y, int nrows) {
    extern __shared__ float sh[];
    float* W_sh = sh;                    // 128*NOUT
    float* x_sh = sh + 128 * NOUT;       // 4*128
    const int tid = threadIdx.x;         // blockDim.x == NOUT
    for (int i = tid; i < 128 * NOUT; i += NOUT) W_sh[i] = W[i];
    const float bb = B[tid];
    const int base = blockIdx.x * 64;
    for (int g = 0; g < 64; g += 4) {
        __syncthreads();
        for (int i = tid; i < 4 * 128; i += NOUT) {
            int r = base + g + (i >> 7);
            x_sh[i] = (r < nrows) ? X[(size_t)r * 128 + (i & 127)] : 0.f;
        }
        __syncthreads();
        float a0 = 0.f, a1 = 0.f, a2 = 0.f, a3 = 0.f;
#pragma unroll 4
        for (int k = 0; k < 128; k++) {
            float w = W_sh[k * NOUT + tid];
            a0 += x_sh[k] * w;
            a1 += x_sh[128 + k] * w;
            a2 += x_sh[256 + k] * w;
            a3 += x_sh[384 + k] * w;
        }
        int r = base + g;
        if (r     < nrows) Y[(size_t)(r    ) * NOUT + tid] = a0 + bb;
        if (r + 1 < nrows) Y[(size_t)(r + 1) * NOUT + tid] = a1 + bb;
        if (r + 2 < nrows) Y[(size_t)(r + 2) * NOUT + tid] = a2 + bb;
        if (r + 3 < nrows) Y[(size_t)(r + 3) * NOUT + tid] = a3 + bb;
    }
}

// ---------------- layer 1: edge score + segment max (thread = (edge, head)) ----------------
__global__ void k_score1(const int* __restrict__ ei, const float* __restrict__ att,
                         int E, int ET) {
    int t = blockIdx.x * blockDim.x + threadIdx.x;
    if (t >= ET * 8) return;
    const int is64 = g_is64;
    int e = t >> 3, h = t & 7;
    int s, d;
    if (e < E) edge_sd(ei, e, E, is64, s, d);
    else       s = d = e - E;
    const float4* xl = (const float4*)(g_xl1 + (size_t)s * 128 + h * 16);
    const float4* xr = (const float4*)(g_xr1 + (size_t)d * 128 + h * 16);
    const float4* at = (const float4*)(att + h * 16);
    float sc = 0.f;
#pragma unroll
    for (int i = 0; i < 4; i++) {
        float4 a = __ldg(xl + i), b = __ldg(xr + i), w = __ldg(at + i);
        sc += lrelu(a.x + b.x) * w.x;
        sc += lrelu(a.y + b.y) * w.y;
        sc += lrelu(a.z + b.z) * w.z;
        sc += lrelu(a.w + b.w) * w.w;
    }
    g_score1[t] = sc;
    atomicMax(&g_mx1[d * 8 + h], enc_f(sc));
}

// ---------------- layer 1: exp + denom + unnormalized aggregation ----------------
__global__ void k_agg1(const int* __restrict__ ei, int E, int ET) {
    int t = blockIdx.x * blockDim.x + threadIdx.x;
    if (t >= ET * 8) return;
    const int is64 = g_is64;
    int e = t >> 3, h = t & 7;
    int s, d;
    if (e < E) edge_sd(ei, e, E, is64, s, d);
    else       s = d = e - E;
    float a = __expf(g_score1[t] - dec_f(g_mx1[d * 8 + h]));
    atomicAdd(&g_den1[d * 8 + h], a);
    const float4* xl = (const float4*)(g_xl1 + (size_t)s * 128 + h * 16);
    float* out = g_agg1 + (size_t)d * 128 + h * 16;
#pragma unroll
    for (int i = 0; i < 4; i++) {
        float4 v = __ldg(xl + i);
        atomicAdd(out + 4 * i + 0, v.x * a);
        atomicAdd(out + 4 * i + 1, v.y * a);
        atomicAdd(out + 4 * i + 2, v.z * a);
        atomicAdd(out + 4 * i + 3, v.w * a);
    }
}

// ---------------- layer 1: normalize + bias + elu ----------------
__global__ void k_node1(const float* __restrict__ bias, int N) {
    int t = blockIdx.x * blockDim.x + threadIdx.x;
    if (t >= N * 128) return;
    int n = t >> 7, hc = t & 127, h = hc >> 4;
    float v = g_agg1[t] / g_den1[n * 8 + h] + __ldg(bias + hc);
    g_h[t] = v > 0.f ? v : expm1f(v);
}

// ---------------- layer 2: edge score + segment max (warp = edge) ----------------
__global__ void k_score2(const int* __restrict__ ei, const float* __restrict__ att2,
                         int E, int ET) {
    int gt = blockIdx.x * blockDim.x + threadIdx.x;
    int e = gt >> 5, lane = gt & 31;
    if (e >= ET) return;
    const int is64 = g_is64;
    int s, d;
    if (e < E) edge_sd(ei, e, E, is64, s, d);
    else       s = d = e - E;
    float a0 = __ldg(g_xl2 + (size_t)s * 64 + lane);
    float b0 = __ldg(g_xr2 + (size_t)d * 64 + lane);
    float a1 = __ldg(g_xl2 + (size_t)s * 64 + lane + 32);
    float b1 = __ldg(g_xr2 + (size_t)d * 64 + lane + 32);
    float sc = lrelu(a0 + b0) * __ldg(att2 + lane) + lrelu(a1 + b1) * __ldg(att2 + lane + 32);
#pragma unroll
    for (int o = 16; o; o >>= 1) sc += __shfl_xor_sync(0xFFFFFFFFu, sc, o);
    if (lane == 0) {
        g_score2[e] = sc;
        atomicMax(&g_mx2[d], enc_f(sc));
    }
}

// ---------------- layer 2: exp + denom + aggregation into d_out ----------------
__global__ void k_agg2(const int* __restrict__ ei, float* __restrict__ dout,
                       int E, int ET) {
    int gt = blockIdx.x * blockDim.x + threadIdx.x;
    int e = gt >> 5, lane = gt & 31;
    if (e >= ET) return;
    const int is64 = g_is64;
    int s, d;
    if (e < E) edge_sd(ei, e, E, is64, s, d);
    else       s = d = e - E;
    float a = 0.f;
    if (lane == 0) a = __expf(g_score2[e] - dec_f(g_mx2[d]));
    a = __shfl_sync(0xFFFFFFFFu, a, 0);
    if (lane == 0) atomicAdd(&g_den2[d], a);
    float v0 = __ldg(g_xl2 + (size_t)s * 64 + lane);
    float v1 = __ldg(g_xl2 + (size_t)s * 64 + lane + 32);
    atomicAdd(dout + (size_t)d * 64 + lane,      v0 * a);
    atomicAdd(dout + (size_t)d * 64 + lane + 32, v1 * a);
}

// ---------------- layer 2: normalize + bias ----------------
__global__ void k_node2(float* __restrict__ dout, const float* __restrict__ bias2, int N) {
    int t = blockIdx.x * blockDim.x + threadIdx.x;
    if (t >= N * 64) return;
    int n = t >> 6, c = t & 63;
    dout[t] = dout[t] / g_den2[n] + __ldg(bias2 + c);
}

// ---------------- launch ----------------
static inline int cdiv(long long a, int b) { return (int)((a + b - 1) / b); }

extern "C" void kernel_launch(void* const* d_in, const int* in_sizes, int n_in,
                              void* d_out, int out_size) {
    const float* x    = (const float*)d_in[0];
    const int*   ei   = (const int*)d_in[1];   // int32 view; dtype auto-detected
    const float* Wl1  = (const float*)d_in[2];
    const float* bl1  = (const float*)d_in[3];
    const float* Wr1  = (const float*)d_in[4];
    const float* br1  = (const float*)d_in[5];
    const float* att1 = (const float*)d_in[6];
    const float* bias1= (const float*)d_in[7];
    const float* Wl2  = (const float*)d_in[8];
    const float* bl2  = (const float*)d_in[9];
    const float* Wr2  = (const float*)d_in[10];
    const float* br2  = (const float*)d_in[11];
    const float* att2 = (const float*)d_in[12];
    const float* bias2= (const float*)d_in[13];
    float* dout = (float*)d_out;

    const int N  = in_sizes[0] / 128;
    const int E  = in_sizes[1] / 2;   // element count is 2*E for either dtype
    const int ET = E + N;

    float *xl1, *xr1, *h, *xl2, *xr2;
    cudaGetSymbolAddress((void**)&xl1, g_xl1);
    cudaGetSymbolAddress((void**)&xr1, g_xr1);
    cudaGetSymbolAddress((void**)&h,   g_h);
    cudaGetSymbolAddress((void**)&xl2, g_xl2);
    cudaGetSymbolAddress((void**)&xr2, g_xr2);

    const int smem128 = (128 * 128 + 4 * 128) * sizeof(float); // ~67.5 KB
    const int smem64  = (128 * 64  + 4 * 128) * sizeof(float); // ~34.8 KB
    cudaFuncSetAttribute(k_gemm<128>, cudaFuncAttributeMaxDynamicSharedMemorySize, smem128);
    cudaFuncSetAttribute(k_gemm<64>,  cudaFuncAttributeMaxDynamicSharedMemorySize, smem64);

    // dtype detection + init accumulators
    k_detect<<<1, 256>>>(ei, E);
    k_init<<<cdiv((long long)N * 128, 256), 256>>>(dout, N);

    // layer 1 linear transforms
    k_gemm<128><<<cdiv(N, 64), 128, smem128>>>(x, Wl1, bl1, xl1, N);
    k_gemm<128><<<cdiv(N, 64), 128, smem128>>>(x, Wr1, br1, xr1, N);

    // layer 1 attention
    k_score1<<<cdiv((long long)ET * 8, 256), 256>>>(ei, att1, E, ET);
    k_agg1  <<<cdiv((long long)ET * 8, 256), 256>>>(ei, E, ET);
    k_node1 <<<cdiv((long long)N * 128, 256), 256>>>(bias1, N);

    // layer 2 linear transforms
    k_gemm<64><<<cdiv(N, 64), 64, smem64>>>(h, Wl2, bl2, xl2, N);
    k_gemm<64><<<cdiv(N, 64), 64, smem64>>>(h, Wr2, br2, xr2, N);

    // layer 2 attention
    k_score2<<<cdiv((long long)ET * 32, 256), 256>>>(ei, att2, E, ET);
    k_agg2  <<<cdiv((long long)ET * 32, 256), 256>>>(ei, dout, E, ET);
    k_node2 <<<cdiv((long long)N * 64, 256), 256>>>(dout, bias2, N);
}

// round 3
// speedup vs baseline: 3.7674x; 3.7674x over previous
#include <cuda_runtime.h>

#define NN_CAP 100000
#define EE_CAP 1600000

// ---------------- scratch (device globals) ----------------
__device__ int   g_is64;
__device__ int   g_cnt[NN_CAP];
__device__ int   g_off[NN_CAP + 1];
__device__ int   g_cur[NN_CAP];
__device__ int   g_ssrc[EE_CAP];               // edge srcs sorted by dst
__device__ float g_xl1[(size_t)NN_CAP * 128];
__device__ float g_xr1[(size_t)NN_CAP * 128];
__device__ float g_h  [(size_t)NN_CAP * 128];
__device__ float g_xl2[(size_t)NN_CAP * 64];
__device__ float g_xr2[(size_t)NN_CAP * 64];

// ---------------- helpers ----------------
__device__ __forceinline__ float lrelu(float v) { return v > 0.f ? v : 0.2f * v; }

__device__ __forceinline__ int edge_dst(const int* __restrict__ ei, int e, int E, int is64) {
    return is64 ? ei[2 * (E + e)] : ei[E + e];
}
__device__ __forceinline__ int edge_src(const int* __restrict__ ei, int e, int E, int is64) {
    return is64 ? ei[2 * e] : ei[e];
}

// ---------------- dtype detection: int64 values < 2^31 have zero odd slots ----------------
__global__ void k_detect(const int* __restrict__ ei, int E) {
    __shared__ int nz;
    if (threadIdx.x == 0) nz = 0;
    __syncthreads();
    int cnt = E < 4096 ? E : 4096;
    for (int i = threadIdx.x; i < cnt; i += blockDim.x)
        if (ei[2 * i + 1] != 0) nz = 1;
    __syncthreads();
    if (threadIdx.x == 0) g_is64 = (nz == 0) ? 1 : 0;
}

// ---------------- CSR build ----------------
__global__ void k_zero_cnt(int N) {
    int t = blockIdx.x * blockDim.x + threadIdx.x;
    if (t < N) g_cnt[t] = 0;
}

__global__ void k_hist(const int* __restrict__ ei, int E) {
    int e = blockIdx.x * blockDim.x + threadIdx.x;
    if (e >= E) return;
    atomicAdd(&g_cnt[edge_dst(ei, e, E, g_is64)], 1);
}

// single-block exclusive scan (1024 threads), also primes g_cur
__global__ void k_scan(int N) {
    __shared__ int sh[1024];
    __shared__ int carry_s;
    if (threadIdx.x == 0) carry_s = 0;
    __syncthreads();
    for (int base = 0; base < N; base += 1024) {
        int i = base + threadIdx.x;
        int v = (i < N) ? g_cnt[i] : 0;
        sh[threadIdx.x] = v;
        __syncthreads();
        for (int off = 1; off < 1024; off <<= 1) {
            int t = (threadIdx.x >= off) ? sh[threadIdx.x - off] : 0;
            __syncthreads();
            sh[threadIdx.x] += t;
            __syncthreads();
        }
        int carry = carry_s;
        if (i < N) { int o = carry + sh[threadIdx.x] - v; g_off[i] = o; g_cur[i] = o; }
        __syncthreads();
        if (threadIdx.x == 0) carry_s = carry + sh[1023];
        __syncthreads();
    }
    if (threadIdx.x == 0) g_off[N] = carry_s;
}

__global__ void k_scatter(const int* __restrict__ ei, int E) {
    int e = blockIdx.x * blockDim.x + threadIdx.x;
    if (e >= E) return;
    int is64 = g_is64;
    int s = edge_src(ei, e, E, is64), d = edge_dst(ei, e, E, is64);
    int pos = atomicAdd(&g_cur[d], 1);
    g_ssrc[pos] = s;
}

// ---------------- GEMM 128->128: Y = X@W + B ----------------
// block 256 = 32 colgroups x 8 rowgroups; tile 64 rows x 128 cols; K split 2x64
__global__ void k_gemm128(const float* __restrict__ X, const float* __restrict__ W,
                          const float* __restrict__ B, float* __restrict__ Y, int nrows) {
    __shared__ float W_sh[64 * 128];   // 32 KB
    __shared__ float x_sh[64 * 64];    // 16 KB
    const int tid = threadIdx.x;
    const int cg = tid & 31, rg = tid >> 5;
    const int base = blockIdx.x * 64;
    float acc[8][4];
#pragma unroll
    for (int r = 0; r < 8; r++) { acc[r][0] = acc[r][1] = acc[r][2] = acc[r][3] = 0.f; }

    for (int kt = 0; kt < 2; kt++) {
        __syncthreads();
#pragma unroll
        for (int i = tid * 4; i < 64 * 128; i += 1024)
            *(float4*)&W_sh[i] = *(const float4*)&W[kt * 8192 + i];
#pragma unroll
        for (int i = tid * 4; i < 64 * 64; i += 1024) {
            int r = i >> 6, k = i & 63;
            int row = base + r;
            float4 v = make_float4(0.f, 0.f, 0.f, 0.f);
            if (row < nrows) v = *(const float4*)&X[(size_t)row * 128 + kt * 64 + k];
            *(float4*)&x_sh[i] = v;
        }
        __syncthreads();
#pragma unroll 8
        for (int k = 0; k < 64; k++) {
            float4 w = *(float4*)&W_sh[k * 128 + cg * 4];
#pragma unroll
            for (int r = 0; r < 8; r++) {
                float xv = x_sh[(rg * 8 + r) * 64 + k];
                acc[r][0] += xv * w.x; acc[r][1] += xv * w.y;
                acc[r][2] += xv * w.z; acc[r][3] += xv * w.w;
            }
        }
    }
    float4 b4 = *(const float4*)&B[cg * 4];
#pragma unroll
    for (int r = 0; r < 8; r++) {
        int row = base + rg * 8 + r;
        if (row < nrows) {
            float4 o = make_float4(acc[r][0] + b4.x, acc[r][1] + b4.y,
                                   acc[r][2] + b4.z, acc[r][3] + b4.w);
            *(float4*)&Y[(size_t)row * 128 + cg * 4] = o;
        }
    }
}

// ---------------- GEMM 128->64: Y = X@W + B ----------------
// block 256 = 16 colgroups x 16 rowgroups; tile 64 rows x 64 cols; K split 2x64
__global__ void k_gemm64(const float* __restrict__ X, const float* __restrict__ W,
                         const float* __restrict__ B, float* __restrict__ Y, int nrows) {
    __shared__ float W_sh[64 * 64];    // 16 KB
    __shared__ float x_sh[64 * 64];    // 16 KB
    const int tid = threadIdx.x;
    const int cg = tid & 15, rg = tid >> 4;
    const int base = blockIdx.x * 64;
    float acc[4][4];
#pragma unroll
    for (int r = 0; r < 4; r++) { acc[r][0] = acc[r][1] = acc[r][2] = acc[r][3] = 0.f; }

    for (int kt = 0; kt < 2; kt++) {
        __syncthreads();
#pragma unroll
        for (int i = tid * 4; i < 64 * 64; i += 1024)
            *(float4*)&W_sh[i] = *(const float4*)&W[kt * 4096 + i];
#pragma unroll
        for (int i = tid * 4; i < 64 * 64; i += 1024) {
            int r = i >> 6, k = i & 63;
            int row = base + r;
            float4 v = make_float4(0.f, 0.f, 0.f, 0.f);
            if (row < nrows) v = *(const float4*)&X[(size_t)row * 128 + kt * 64 + k];
            *(float4*)&x_sh[i] = v;
        }
        __syncthreads();
#pragma unroll 8
        for (int k = 0; k < 64; k++) {
            float4 w = *(float4*)&W_sh[k * 64 + cg * 4];
#pragma unroll
            for (int r = 0; r < 4; r++) {
                float xv = x_sh[(rg * 4 + r) * 64 + k];
                acc[r][0] += xv * w.x; acc[r][1] += xv * w.y;
                acc[r][2] += xv * w.z; acc[r][3] += xv * w.w;
            }
        }
    }
    float4 b4 = *(const float4*)&B[cg * 4];
#pragma unroll
    for (int r = 0; r < 4; r++) {
        int row = base + rg * 4 + r;
        if (row < nrows) {
            float4 o = make_float4(acc[r][0] + b4.x, acc[r][1] + b4.y,
                                   acc[r][2] + b4.z, acc[r][3] + b4.w);
            *(float4*)&Y[(size_t)row * 64 + cg * 4] = o;
        }
    }
}

// ---------------- layer 1 fused attention: warp per node, online softmax ----------------
// H=8 heads x C=16; lane l owns channels 4l..4l+3; head = l>>2 (4-lane groups)
__global__ void k_attn1(const float* __restrict__ att, const float* __restrict__ bias, int N) {
    int node = blockIdx.x * 8 + (threadIdx.x >> 5);
    int lane = threadIdx.x & 31;
    if (node >= N) return;
    const int d = node;

    float4 xr = *(const float4*)&g_xr1[(size_t)d * 128 + lane * 4];
    float4 at = *(const float4*)&att[lane * 4];

    // self-loop seeds the online softmax
    float4 xl = *(const float4*)&g_xl1[(size_t)d * 128 + lane * 4];
    float sc = lrelu(xl.x + xr.x) * at.x + lrelu(xl.y + xr.y) * at.y +
               lrelu(xl.z + xr.z) * at.z + lrelu(xl.w + xr.w) * at.w;
    sc += __shfl_xor_sync(0xFFFFFFFFu, sc, 1);
    sc += __shfl_xor_sync(0xFFFFFFFFu, sc, 2);
    float m = sc, den = 1.f;
    float4 acc = xl;

    int beg = g_off[d], end = g_off[d + 1];
    for (int j = beg; j < end; j++) {
        int s = g_ssrc[j];
        xl = *(const float4*)&g_xl1[(size_t)s * 128 + lane * 4];
        sc = lrelu(xl.x + xr.x) * at.x + lrelu(xl.y + xr.y) * at.y +
             lrelu(xl.z + xr.z) * at.z + lrelu(xl.w + xr.w) * at.w;
        sc += __shfl_xor_sync(0xFFFFFFFFu, sc, 1);
        sc += __shfl_xor_sync(0xFFFFFFFFu, sc, 2);
        float nm = fmaxf(m, sc);
        float cold = __expf(m - nm), wgt = __expf(sc - nm);
        den = den * cold + wgt;
        acc.x = acc.x * cold + wgt * xl.x;
        acc.y = acc.y * cold + wgt * xl.y;
        acc.z = acc.z * cold + wgt * xl.z;
        acc.w = acc.w * cold + wgt * xl.w;
        m = nm;
    }
    float inv = 1.f / den;
    float4 bi = *(const float4*)&bias[lane * 4];
    float4 o;
    o.x = acc.x * inv + bi.x; o.y = acc.y * inv + bi.y;
    o.z = acc.z * inv + bi.z; o.w = acc.w * inv + bi.w;
    // ELU
    o.x = o.x > 0.f ? o.x : expm1f(o.x);
    o.y = o.y > 0.f ? o.y : expm1f(o.y);
    o.z = o.z > 0.f ? o.z : expm1f(o.z);
    o.w = o.w > 0.f ? o.w : expm1f(o.w);
    *(float4*)&g_h[(size_t)d * 128 + lane * 4] = o;
}

// ---------------- layer 2 fused attention: warp per node, C=64, H=1 ----------------
__global__ void k_attn2(const float* __restrict__ att2, const float* __restrict__ bias2,
                        float* __restrict__ dout, int N) {
    int node = blockIdx.x * 8 + (threadIdx.x >> 5);
    int lane = threadIdx.x & 31;
    if (node >= N) return;
    const int d = node;

    float xr0 = g_xr2[(size_t)d * 64 + lane];
    float xr1 = g_xr2[(size_t)d * 64 + lane + 32];
    float a0 = att2[lane], a1 = att2[lane + 32];

    // self-loop
    float l0 = g_xl2[(size_t)d * 64 + lane];
    float l1 = g_xl2[(size_t)d * 64 + lane + 32];
    float sc = lrelu(l0 + xr0) * a0 + lrelu(l1 + xr1) * a1;
#pragma unroll
    for (int o = 16; o; o >>= 1) sc += __shfl_xor_sync(0xFFFFFFFFu, sc, o);
    float m = sc, den = 1.f;
    float acc0 = l0, acc1 = l1;

    int beg = g_off[d], end = g_off[d + 1];
    for (int j = beg; j < end; j++) {
        int s = g_ssrc[j];
        l0 = g_xl2[(size_t)s * 64 + lane];
        l1 = g_xl2[(size_t)s * 64 + lane + 32];
        sc = lrelu(l0 + xr0) * a0 + lrelu(l1 + xr1) * a1;
#pragma unroll
        for (int o = 16; o; o >>= 1) sc += __shfl_xor_sync(0xFFFFFFFFu, sc, o);
        float nm = fmaxf(m, sc);
        float cold = __expf(m - nm), wgt = __expf(sc - nm);
        den = den * cold + wgt;
        acc0 = acc0 * cold + wgt * l0;
        acc1 = acc1 * cold + wgt * l1;
        m = nm;
    }
    float inv = 1.f / den;
    dout[(size_t)d * 64 + lane]      = acc0 * inv + bias2[lane];
    dout[(size_t)d * 64 + lane + 32] = acc1 * inv + bias2[lane + 32];
}

// ---------------- launch ----------------
static inline int cdiv(long long a, int b) { return (int)((a + b - 1) / b); }

extern "C" void kernel_launch(void* const* d_in, const int* in_sizes, int n_in,
                              void* d_out, int out_size) {
    const float* x    = (const float*)d_in[0];
    const int*   ei   = (const int*)d_in[1];   // int32 view; dtype auto-detected
    const float* Wl1  = (const float*)d_in[2];
    const float* bl1  = (const float*)d_in[3];
    const float* Wr1  = (const float*)d_in[4];
    const float* br1  = (const float*)d_in[5];
    const float* att1 = (const float*)d_in[6];
    const float* bias1= (const float*)d_in[7];
    const float* Wl2  = (const float*)d_in[8];
    const float* bl2  = (const float*)d_in[9];
    const float* Wr2  = (const float*)d_in[10];
    const float* br2  = (const float*)d_in[11];
    const float* att2 = (const float*)d_in[12];
    const float* bias2= (const float*)d_in[13];
    float* dout = (float*)d_out;

    const int N = in_sizes[0] / 128;
    const int E = in_sizes[1] / 2;

    float *xl1, *xr1, *h, *xl2, *xr2;
    cudaGetSymbolAddress((void**)&xl1, g_xl1);
    cudaGetSymbolAddress((void**)&xr1, g_xr1);
    cudaGetSymbolAddress((void**)&h,   g_h);
    cudaGetSymbolAddress((void**)&xl2, g_xl2);
    cudaGetSymbolAddress((void**)&xr2, g_xr2);

    // dtype + CSR build (reused by both layers)
    k_detect <<<1, 256>>>(ei, E);
    k_zero_cnt<<<cdiv(N, 256), 256>>>(N);
    k_hist   <<<cdiv(E, 256), 256>>>(ei, E);
    k_scan   <<<1, 1024>>>(N);
    k_scatter<<<cdiv(E, 256), 256>>>(ei, E);

    // layer 1
    k_gemm128<<<cdiv(N, 64), 256>>>(x, Wl1, bl1, xl1, N);
    k_gemm128<<<cdiv(N, 64), 256>>>(x, Wr1, br1, xr1, N);
    k_attn1  <<<cdiv(N, 8), 256>>>(att1, bias1, N);

    // layer 2
    k_gemm64 <<<cdiv(N, 64), 256>>>(h, Wl2, bl2, xl2, N);
    k_gemm64 <<<cdiv(N, 64), 256>>>(h, Wr2, br2, xr2, N);
    k_attn2  <<<cdiv(N, 8), 256>>>(att2, bias2, dout, N);
}

// round 4
// speedup vs baseline: 4.6824x; 1.2429x over previous
#include <cuda_runtime.h>

#define NN_CAP 100000
#define EE_CAP 1600000
#define SCAN_B 1024

// ---------------- scratch (device globals) ----------------
__device__ int   g_is64;
__device__ int   g_cnt[NN_CAP];
__device__ int   g_off[NN_CAP + 1];
__device__ int   g_cur[NN_CAP];
__device__ int   g_bsum[(NN_CAP + SCAN_B - 1) / SCAN_B];
__device__ int   g_bpre[(NN_CAP + SCAN_B - 1) / SCAN_B];
__device__ int   g_ssrc[EE_CAP];               // edge srcs sorted by dst
__device__ float g_xl1[(size_t)NN_CAP * 128];
__device__ float g_xr1[(size_t)NN_CAP * 128];
__device__ float g_h  [(size_t)NN_CAP * 128];
__device__ float g_xl2[(size_t)NN_CAP * 64];
__device__ float g_xr2[(size_t)NN_CAP * 64];

// ---------------- helpers ----------------
__device__ __forceinline__ float lrelu(float v) { return v > 0.f ? v : 0.2f * v; }

__device__ __forceinline__ int edge_dst(const int* __restrict__ ei, int e, int E, int is64) {
    return is64 ? ei[2 * (E + e)] : ei[E + e];
}
__device__ __forceinline__ int edge_src(const int* __restrict__ ei, int e, int E, int is64) {
    return is64 ? ei[2 * e] : ei[e];
}

// ---------------- dtype detection: int64 values < 2^31 have zero odd slots ----------------
__global__ void k_detect(const int* __restrict__ ei, int E) {
    __shared__ int nz;
    if (threadIdx.x == 0) nz = 0;
    __syncthreads();
    int cnt = E < 4096 ? E : 4096;
    for (int i = threadIdx.x; i < cnt; i += blockDim.x)
        if (ei[2 * i + 1] != 0) nz = 1;
    __syncthreads();
    if (threadIdx.x == 0) g_is64 = (nz == 0) ? 1 : 0;
}

// ---------------- CSR build ----------------
__global__ void k_zero_cnt(int N) {
    int t = blockIdx.x * blockDim.x + threadIdx.x;
    if (t < N) g_cnt[t] = 0;
}

__global__ void k_hist(const int* __restrict__ ei, int E) {
    int e = blockIdx.x * blockDim.x + threadIdx.x;
    if (e >= E) return;
    atomicAdd(&g_cnt[edge_dst(ei, e, E, g_is64)], 1);
}

// stage 1: per-block exclusive scan of 1024 counts; emit block sum
__global__ void k_scan1(int N) {
    __shared__ int wsum[32];
    const int tid = threadIdx.x;
    const int i = blockIdx.x * SCAN_B + tid;
    const int lane = tid & 31, wid = tid >> 5;
    int v = (i < N) ? g_cnt[i] : 0;
    // warp inclusive scan
    int incl = v;
#pragma unroll
    for (int o = 1; o < 32; o <<= 1) {
        int t = __shfl_up_sync(0xFFFFFFFFu, incl, o);
        if (lane >= o) incl += t;
    }
    if (lane == 31) wsum[wid] = incl;
    __syncthreads();
    if (wid == 0) {
        int w = wsum[lane];
        int wi = w;
#pragma unroll
        for (int o = 1; o < 32; o <<= 1) {
            int t = __shfl_up_sync(0xFFFFFFFFu, wi, o);
            if (lane >= o) wi += t;
        }
        wsum[lane] = wi - w;  // exclusive warp prefix
        if (lane == 31) g_bsum[blockIdx.x] = wi;  // block total
    }
    __syncthreads();
    if (i < N) g_off[i] = incl - v + wsum[wid];   // local exclusive prefix
}

// stage 2: single small block scans block sums (NB <= 128)
__global__ void k_scan2(int NB, int N) {
    const int lane = threadIdx.x & 31, wid = threadIdx.x >> 5;
    __shared__ int wsum[4];
    int v = (threadIdx.x < NB) ? g_bsum[threadIdx.x] : 0;
    int incl = v;
#pragma unroll
    for (int o = 1; o < 32; o <<= 1) {
        int t = __shfl_up_sync(0xFFFFFFFFu, incl, o);
        if (lane >= o) incl += t;
    }
    if (lane == 31) wsum[wid] = incl;
    __syncthreads();
    int pre = 0;
    for (int w = 0; w < wid; w++) pre += wsum[w];
    if (threadIdx.x < NB) g_bpre[threadIdx.x] = pre + incl - v;
    if (threadIdx.x == 127) g_off[N] = pre + incl;  // grand total (E)
}

// stage 3: add block prefixes, prime cursor
__global__ void k_scan3(int N) {
    int t = blockIdx.x * blockDim.x + threadIdx.x;
    if (t >= N) return;
    int o = g_off[t] + g_bpre[t >> 10];
    g_off[t] = o;
    g_cur[t] = o;
}

__global__ void k_scatter(const int* __restrict__ ei, int E) {
    int e = blockIdx.x * blockDim.x + threadIdx.x;
    if (e >= E) return;
    int is64 = g_is64;
    int s = edge_src(ei, e, E, is64), d = edge_dst(ei, e, E, is64);
    int pos = atomicAdd(&g_cur[d], 1);
    g_ssrc[pos] = s;
}

// ---------------- GEMM 128->128: Y = X@W + B ----------------
__global__ void k_gemm128(const float* __restrict__ X, const float* __restrict__ W,
                          const float* __restrict__ B, float* __restrict__ Y, int nrows) {
    __shared__ float W_sh[64 * 128];   // 32 KB
    __shared__ float x_sh[64 * 64];    // 16 KB
    const int tid = threadIdx.x;
    const int cg = tid & 31, rg = tid >> 5;
    const int base = blockIdx.x * 64;
    float acc[8][4];
#pragma unroll
    for (int r = 0; r < 8; r++) { acc[r][0] = acc[r][1] = acc[r][2] = acc[r][3] = 0.f; }

    for (int kt = 0; kt < 2; kt++) {
        __syncthreads();
#pragma unroll
        for (int i = tid * 4; i < 64 * 128; i += 1024)
            *(float4*)&W_sh[i] = *(const float4*)&W[kt * 8192 + i];
#pragma unroll
        for (int i = tid * 4; i < 64 * 64; i += 1024) {
            int r = i >> 6, k = i & 63;
            int row = base + r;
            float4 v = make_float4(0.f, 0.f, 0.f, 0.f);
            if (row < nrows) v = *(const float4*)&X[(size_t)row * 128 + kt * 64 + k];
            *(float4*)&x_sh[i] = v;
        }
        __syncthreads();
#pragma unroll 8
        for (int k = 0; k < 64; k++) {
            float4 w = *(float4*)&W_sh[k * 128 + cg * 4];
#pragma unroll
            for (int r = 0; r < 8; r++) {
                float xv = x_sh[(rg * 8 + r) * 64 + k];
                acc[r][0] += xv * w.x; acc[r][1] += xv * w.y;
                acc[r][2] += xv * w.z; acc[r][3] += xv * w.w;
            }
        }
    }
    float4 b4 = *(const float4*)&B[cg * 4];
#pragma unroll
    for (int r = 0; r < 8; r++) {
        int row = base + rg * 8 + r;
        if (row < nrows) {
            float4 o = make_float4(acc[r][0] + b4.x, acc[r][1] + b4.y,
                                   acc[r][2] + b4.z, acc[r][3] + b4.w);
            *(float4*)&Y[(size_t)row * 128 + cg * 4] = o;
        }
    }
}

// ---------------- GEMM 128->64: Y = X@W + B ----------------
__global__ void k_gemm64(const float* __restrict__ X, const float* __restrict__ W,
                         const float* __restrict__ B, float* __restrict__ Y, int nrows) {
    __shared__ float W_sh[64 * 64];    // 16 KB
    __shared__ float x_sh[64 * 64];    // 16 KB
    const int tid = threadIdx.x;
    const int cg = tid & 15, rg = tid >> 4;
    const int base = blockIdx.x * 64;
    float acc[4][4];
#pragma unroll
    for (int r = 0; r < 4; r++) { acc[r][0] = acc[r][1] = acc[r][2] = acc[r][3] = 0.f; }

    for (int kt = 0; kt < 2; kt++) {
        __syncthreads();
#pragma unroll
        for (int i = tid * 4; i < 64 * 64; i += 1024)
            *(float4*)&W_sh[i] = *(const float4*)&W[kt * 4096 + i];
#pragma unroll
        for (int i = tid * 4; i < 64 * 64; i += 1024) {
            int r = i >> 6, k = i & 63;
            int row = base + r;
            float4 v = make_float4(0.f, 0.f, 0.f, 0.f);
            if (row < nrows) v = *(const float4*)&X[(size_t)row * 128 + kt * 64 + k];
            *(float4*)&x_sh[i] = v;
        }
        __syncthreads();
#pragma unroll 8
        for (int k = 0; k < 64; k++) {
            float4 w = *(float4*)&W_sh[k * 64 + cg * 4];
#pragma unroll
            for (int r = 0; r < 4; r++) {
                float xv = x_sh[(rg * 4 + r) * 64 + k];
                acc[r][0] += xv * w.x; acc[r][1] += xv * w.y;
                acc[r][2] += xv * w.z; acc[r][3] += xv * w.w;
            }
        }
    }
    float4 b4 = *(const float4*)&B[cg * 4];
#pragma unroll
    for (int r = 0; r < 4; r++) {
        int row = base + rg * 4 + r;
        if (row < nrows) {
            float4 o = make_float4(acc[r][0] + b4.x, acc[r][1] + b4.y,
                                   acc[r][2] + b4.z, acc[r][3] + b4.w);
            *(float4*)&Y[(size_t)row * 64 + cg * 4] = o;
        }
    }
}

// ---------------- layer 1 fused attention: warp per node, online softmax ----------------
// H=8 heads x C=16; lane l owns channels 4l..4l+3; head = l>>2 (4-lane groups)
__global__ void k_attn1(const float* __restrict__ att, const float* __restrict__ bias, int N) {
    int node = blockIdx.x * 8 + (threadIdx.x >> 5);
    int lane = threadIdx.x & 31;
    if (node >= N) return;
    const int d = node;

    float4 xr = *(const float4*)&g_xr1[(size_t)d * 128 + lane * 4];
    float4 at = *(const float4*)&att[lane * 4];

    // self-loop seeds the online softmax
    float4 self = *(const float4*)&g_xl1[(size_t)d * 128 + lane * 4];
    float sc = lrelu(self.x + xr.x) * at.x + lrelu(self.y + xr.y) * at.y +
               lrelu(self.z + xr.z) * at.z + lrelu(self.w + xr.w) * at.w;
    sc += __shfl_xor_sync(0xFFFFFFFFu, sc, 1);
    sc += __shfl_xor_sync(0xFFFFFFFFu, sc, 2);
    float m = sc, den = 1.f;
    float4 acc = self;

    const int beg = g_off[d], end = g_off[d + 1];
    float4 xl;
    if (beg < end) {
        int s0 = __ldg(&g_ssrc[beg]);
        xl = *(const float4*)&g_xl1[(size_t)s0 * 128 + lane * 4];
    }
    for (int j = beg; j < end; j++) {
        float4 cur = xl;
        if (j + 1 < end) {                       // prefetch next row
            int sn = __ldg(&g_ssrc[j + 1]);
            xl = *(const float4*)&g_xl1[(size_t)sn * 128 + lane * 4];
        }
        sc = lrelu(cur.x + xr.x) * at.x + lrelu(cur.y + xr.y) * at.y +
             lrelu(cur.z + xr.z) * at.z + lrelu(cur.w + xr.w) * at.w;
        sc += __shfl_xor_sync(0xFFFFFFFFu, sc, 1);
        sc += __shfl_xor_sync(0xFFFFFFFFu, sc, 2);
        float nm = fmaxf(m, sc);
        float cold = __expf(m - nm), wgt = __expf(sc - nm);
        den = den * cold + wgt;
        acc.x = acc.x * cold + wgt * cur.x;
        acc.y = acc.y * cold + wgt * cur.y;
        acc.z = acc.z * cold + wgt * cur.z;
        acc.w = acc.w * cold + wgt * cur.w;
        m = nm;
    }
    float inv = 1.f / den;
    float4 bi = *(const float4*)&bias[lane * 4];
    float4 o;
    o.x = acc.x * inv + bi.x; o.y = acc.y * inv + bi.y;
    o.z = acc.z * inv + bi.z; o.w = acc.w * inv + bi.w;
    // ELU
    o.x = o.x > 0.f ? o.x : expm1f(o.x);
    o.y = o.y > 0.f ? o.y : expm1f(o.y);
    o.z = o.z > 0.f ? o.z : expm1f(o.z);
    o.w = o.w > 0.f ? o.w : expm1f(o.w);
    *(float4*)&g_h[(size_t)d * 128 + lane * 4] = o;
}

// ---------------- layer 2 fused attention: warp per node, C=64, H=1 ----------------
__global__ void k_attn2(const float* __restrict__ att2, const float* __restrict__ bias2,
                        float* __restrict__ dout, int N) {
    int node = blockIdx.x * 8 + (threadIdx.x >> 5);
    int lane = threadIdx.x & 31;
    if (node >= N) return;
    const int d = node;

    float xr0 = g_xr2[(size_t)d * 64 + lane];
    float xr1 = g_xr2[(size_t)d * 64 + lane + 32];
    float a0 = att2[lane], a1 = att2[lane + 32];

    // self-loop
    float s0 = g_xl2[(size_t)d * 64 + lane];
    float s1 = g_xl2[(size_t)d * 64 + lane + 32];
    float sc = lrelu(s0 + xr0) * a0 + lrelu(s1 + xr1) * a1;
#pragma unroll
    for (int o = 16; o; o >>= 1) sc += __shfl_xor_sync(0xFFFFFFFFu, sc, o);
    float m = sc, den = 1.f;
    float acc0 = s0, acc1 = s1;

    const int beg = g_off[d], end = g_off[d + 1];
    float l0, l1;
    if (beg < end) {
        int sp = __ldg(&g_ssrc[beg]);
        l0 = g_xl2[(size_t)sp * 64 + lane];
        l1 = g_xl2[(size_t)sp * 64 + lane + 32];
    }
    for (int j = beg; j < end; j++) {
        float c0 = l0, c1 = l1;
        if (j + 1 < end) {
            int sn = __ldg(&g_ssrc[j + 1]);
            l0 = g_xl2[(size_t)sn * 64 + lane];
            l1 = g_xl2[(size_t)sn * 64 + lane + 32];
        }
        sc = lrelu(c0 + xr0) * a0 + lrelu(c1 + xr1) * a1;
#pragma unroll
        for (int o = 16; o; o >>= 1) sc += __shfl_xor_sync(0xFFFFFFFFu, sc, o);
        float nm = fmaxf(m, sc);
        float cold = __expf(m - nm), wgt = __expf(sc - nm);
        den = den * cold + wgt;
        acc0 = acc0 * cold + wgt * c0;
        acc1 = acc1 * cold + wgt * c1;
        m = nm;
    }
    float inv = 1.f / den;
    dout[(size_t)d * 64 + lane]      = acc0 * inv + bias2[lane];
    dout[(size_t)d * 64 + lane + 32] = acc1 * inv + bias2[lane + 32];
}

// ---------------- launch ----------------
static inline int cdiv(long long a, int b) { return (int)((a + b - 1) / b); }

extern "C" void kernel_launch(void* const* d_in, const int* in_sizes, int n_in,
                              void* d_out, int out_size) {
    const float* x    = (const float*)d_in[0];
    const int*   ei   = (const int*)d_in[1];   // int32 view; dtype auto-detected
    const float* Wl1  = (const float*)d_in[2];
    const float* bl1  = (const float*)d_in[3];
    const float* Wr1  = (const float*)d_in[4];
    const float* br1  = (const float*)d_in[5];
    const float* att1 = (const float*)d_in[6];
    const float* bias1= (const float*)d_in[7];
    const float* Wl2  = (const float*)d_in[8];
    const float* bl2  = (const float*)d_in[9];
    const float* Wr2  = (const float*)d_in[10];
    const float* br2  = (const float*)d_in[11];
    const float* att2 = (const float*)d_in[12];
    const float* bias2= (const float*)d_in[13];
    float* dout = (float*)d_out;

    const int N = in_sizes[0] / 128;
    const int E = in_sizes[1] / 2;
    const int NB = cdiv(N, SCAN_B);

    float *xl1, *xr1, *h, *xl2, *xr2;
    cudaGetSymbolAddress((void**)&xl1, g_xl1);
    cudaGetSymbolAddress((void**)&xr1, g_xr1);
    cudaGetSymbolAddress((void**)&h,   g_h);
    cudaGetSymbolAddress((void**)&xl2, g_xl2);
    cudaGetSymbolAddress((void**)&xr2, g_xr2);

    // dtype + CSR build (reused by both layers)
    k_detect <<<1, 256>>>(ei, E);
    k_zero_cnt<<<cdiv(N, 256), 256>>>(N);
    k_hist   <<<cdiv(E, 256), 256>>>(ei, E);
    k_scan1  <<<NB, SCAN_B>>>(N);
    k_scan2  <<<1, 128>>>(NB, N);
    k_scan3  <<<cdiv(N, 256), 256>>>(N);
    k_scatter<<<cdiv(E, 256), 256>>>(ei, E);

    // layer 1
    k_gemm128<<<cdiv(N, 64), 256>>>(x, Wl1, bl1, xl1, N);
    k_gemm128<<<cdiv(N, 64), 256>>>(x, Wr1, br1, xr1, N);
    k_attn1  <<<cdiv(N, 8), 256>>>(att1, bias1, N);

    // layer 2
    k_gemm64 <<<cdiv(N, 64), 256>>>(h, Wl2, bl2, xl2, N);
    k_gemm64 <<<cdiv(N, 64), 256>>>(h, Wr2, br2, xr2, N);
    k_attn2  <<<cdiv(N, 8), 256>>>(att2, bias2, dout, N);
}

// round 6
// speedup vs baseline: 5.8705x; 1.2537x over previous
#include <cuda_runtime.h>
#include <cuda_bf16.h>
#include <cstdint>

#define NN_CAP 100000
#define EE_CAP 1600000
#define SCAN_B 1024

// ---------------- scratch (device globals) ----------------
__device__ int   g_is64;
__device__ int   g_cnt[NN_CAP];
__device__ int   g_off[NN_CAP + 1];
__device__ int   g_cur[NN_CAP];
__device__ int   g_bsum[(NN_CAP + SCAN_B - 1) / SCAN_B];
__device__ int   g_bpre[(NN_CAP + SCAN_B - 1) / SCAN_B];
__device__ int   g_ssrc[EE_CAP];
__device__ float g_xl1[(size_t)NN_CAP * 128];
__device__ float g_xr1[(size_t)NN_CAP * 128];
__device__ float g_h  [(size_t)NN_CAP * 128];
__device__ float g_xl2[(size_t)NN_CAP * 64];
__device__ float g_xr2[(size_t)NN_CAP * 64];
// split weights, [NOUT][K=128] bf16 (transposed, K-major rows)
__device__ __nv_bfloat16 g_w1lh[16384], g_w1ll[16384], g_w1rh[16384], g_w1rl[16384];
__device__ __nv_bfloat16 g_w2lh[8192],  g_w2ll[8192],  g_w2rh[8192],  g_w2rl[8192];

// ---------------- helpers ----------------
__device__ __forceinline__ uint32_t smem_u32(const void* p) {
    uint32_t a;
    asm("{ .reg .u64 t; cvta.to.shared.u64 t, %1; cvt.u32.u64 %0, t; }" : "=r"(a) : "l"(p));
    return a;
}
__device__ __forceinline__ void ldsm_x4(uint32_t& r0, uint32_t& r1, uint32_t& r2, uint32_t& r3,
                                        uint32_t addr) {
    asm volatile("ldmatrix.sync.aligned.m8n8.x4.shared.b16 {%0,%1,%2,%3}, [%4];"
                 : "=r"(r0), "=r"(r1), "=r"(r2), "=r"(r3) : "r"(addr));
}
__device__ __forceinline__ void mma16816(float* c, const uint32_t* a, const uint32_t* b) {
    asm volatile(
        "mma.sync.aligned.m16n8k16.row.col.f32.bf16.bf16.f32 "
        "{%0,%1,%2,%3}, {%4,%5,%6,%7}, {%8,%9}, {%0,%1,%2,%3};"
        : "+f"(c[0]), "+f"(c[1]), "+f"(c[2]), "+f"(c[3])
        : "r"(a[0]), "r"(a[1]), "r"(a[2]), "r"(a[3]), "r"(b[0]), "r"(b[1]));
}
__device__ __forceinline__ uint32_t pack2(float a, float b) {
    __nv_bfloat162 t = __floats2bfloat162_rn(a, b);
    return *(uint32_t*)&t;
}
__device__ __forceinline__ float lrelu(float v) { return v > 0.f ? v : 0.2f * v; }
__device__ __forceinline__ int edge_dst(const int* __restrict__ ei, int e, int E, int is64) {
    return is64 ? ei[2 * (E + e)] : ei[E + e];
}
__device__ __forceinline__ int edge_src(const int* __restrict__ ei, int e, int E, int is64) {
    return is64 ? ei[2 * e] : ei[e];
}

// ---------------- dtype detection ----------------
__global__ void k_detect(const int* __restrict__ ei, int E) {
    __shared__ int nz;
    if (threadIdx.x == 0) nz = 0;
    __syncthreads();
    int cnt = E < 4096 ? E : 4096;
    for (int i = threadIdx.x; i < cnt; i += blockDim.x)
        if (ei[2 * i + 1] != 0) nz = 1;
    __syncthreads();
    if (threadIdx.x == 0) g_is64 = (nz == 0) ? 1 : 0;
}

// ---------------- CSR build ----------------
__global__ void k_zero_cnt(int N) {
    int t = blockIdx.x * blockDim.x + threadIdx.x;
    if (t < N) g_cnt[t] = 0;
}
__global__ void k_hist(const int* __restrict__ ei, int E) {
    int e = blockIdx.x * blockDim.x + threadIdx.x;
    if (e >= E) return;
    atomicAdd(&g_cnt[edge_dst(ei, e, E, g_is64)], 1);
}
__global__ void k_scan1(int N) {
    __shared__ int wsum[32];
    const int tid = threadIdx.x;
    const int i = blockIdx.x * SCAN_B + tid;
    const int lane = tid & 31, wid = tid >> 5;
    int v = (i < N) ? g_cnt[i] : 0;
    int incl = v;
#pragma unroll
    for (int o = 1; o < 32; o <<= 1) {
        int t = __shfl_up_sync(0xFFFFFFFFu, incl, o);
        if (lane >= o) incl += t;
    }
    if (lane == 31) wsum[wid] = incl;
    __syncthreads();
    if (wid == 0) {
        int w = wsum[lane];
        int wi = w;
#pragma unroll
        for (int o = 1; o < 32; o <<= 1) {
            int t = __shfl_up_sync(0xFFFFFFFFu, wi, o);
            if (lane >= o) wi += t;
        }
        wsum[lane] = wi - w;
        if (lane == 31) g_bsum[blockIdx.x] = wi;
    }
    __syncthreads();
    if (i < N) g_off[i] = incl - v + wsum[wid];
}
__global__ void k_scan2(int NB, int N) {
    const int lane = threadIdx.x & 31, wid = threadIdx.x >> 5;
    __shared__ int wsum[4];
    int v = (threadIdx.x < NB) ? g_bsum[threadIdx.x] : 0;
    int incl = v;
#pragma unroll
    for (int o = 1; o < 32; o <<= 1) {
        int t = __shfl_up_sync(0xFFFFFFFFu, incl, o);
        if (lane >= o) incl += t;
    }
    if (lane == 31) wsum[wid] = incl;
    __syncthreads();
    int pre = 0;
    for (int w = 0; w < wid; w++) pre += wsum[w];
    if (threadIdx.x < NB) g_bpre[threadIdx.x] = pre + incl - v;
    if (threadIdx.x == 127) g_off[N] = pre + incl;
}
__global__ void k_scan3(int N) {
    int t = blockIdx.x * blockDim.x + threadIdx.x;
    if (t >= N) return;
    int o = g_off[t] + g_bpre[t >> 10];
    g_off[t] = o;
    g_cur[t] = o;
}
__global__ void k_scatter(const int* __restrict__ ei, int E) {
    int e = blockIdx.x * blockDim.x + threadIdx.x;
    if (e >= E) return;
    int is64 = g_is64;
    int s = edge_src(ei, e, E, is64), d = edge_dst(ei, e, E, is64);
    int pos = atomicAdd(&g_cur[d], 1);
    g_ssrc[pos] = s;
}

// ---------------- weight prep: transpose + bf16 split ----------------
__global__ void k_wprep(const float* __restrict__ W1l, const float* __restrict__ W1r,
                        const float* __restrict__ W2l, const float* __restrict__ W2r) {
    int t = blockIdx.x * blockDim.x + threadIdx.x;
    const float* W; __nv_bfloat16 *oh, *ol; int NOUT, idx;
    if      (t < 16384)  { W = W1l; oh = g_w1lh; ol = g_w1ll; NOUT = 128; idx = t; }
    else if (t < 32768)  { W = W1r; oh = g_w1rh; ol = g_w1rl; NOUT = 128; idx = t - 16384; }
    else if (t < 40960)  { W = W2l; oh = g_w2lh; ol = g_w2ll; NOUT = 64;  idx = t - 32768; }
    else if (t < 49152)  { W = W2r; oh = g_w2rh; ol = g_w2rl; NOUT = 64;  idx = t - 40960; }
    else return;
    int n = idx >> 7, k = idx & 127;
    float v = W[k * NOUT + n];
    __nv_bfloat16 h = __float2bfloat16_rn(v);
    oh[idx] = h;
    ol[idx] = __float2bfloat16_rn(v - __bfloat162float(h));
}

// ---------------- mma.sync GEMM pair: Yl = X@Wl + bl, Yr = X@Wr + br ----------------
// CTA: 128 rows x 256 threads (8 warps, 4x2). bf16 hi/lo split, 3 passes.
// SMEM tiles padded to 136 halves/row for conflict-free ldmatrix.
template <int NOUT>
__global__ void __launch_bounds__(256, 1) k_gemm_mma(
    const float* __restrict__ X,
    const __nv_bfloat16* __restrict__ Wlh, const __nv_bfloat16* __restrict__ Wll,
    const __nv_bfloat16* __restrict__ Wrh, const __nv_bfloat16* __restrict__ Wrl,
    const float* __restrict__ bl, const float* __restrict__ br,
    float* __restrict__ Yl, float* __restrict__ Yr, int nrows)
{
    constexpr int PITCH = 136;                    // halves per row
    constexpr int ABYTES = 128 * PITCH * 2;       // 34816
    constexpr int BBYTES = NOUT * PITCH * 2;
    constexpr int NFRAG = NOUT / 16;              // n-frags of 8 per warp tile (x2 each pair)
    constexpr int WN = NOUT / 2;

    extern __shared__ char sm[];
    __nv_bfloat16* Ah = (__nv_bfloat16*)sm;
    __nv_bfloat16* Al = (__nv_bfloat16*)(sm + ABYTES);
    __nv_bfloat16* Bt = (__nv_bfloat16*)(sm + 2 * ABYTES);   // 4 tiles: lh, ll, rh, rl

    const int tid = threadIdx.x, wid = tid >> 5, lane = tid & 31;
    const int wm = wid & 3, wn = wid >> 2;
    const int base = blockIdx.x * 128;

    // ---- A tile: fp32 -> hi/lo bf16, padded rows ----
    for (int c = tid; c < 2048; c += 256) {
        int row = c >> 4, col8 = (c & 15) << 3;
        int gr = base + row;
        float4 v0 = make_float4(0.f, 0.f, 0.f, 0.f), v1 = v0;
        if (gr < nrows) {
            v0 = *(const float4*)&X[(size_t)gr * 128 + col8];
            v1 = *(const float4*)&X[(size_t)gr * 128 + col8 + 4];
        }
        float in[8] = {v0.x, v0.y, v0.z, v0.w, v1.x, v1.y, v1.z, v1.w};
        float hf[8], lf[8];
#pragma unroll
        for (int i = 0; i < 8; i++) {
            __nv_bfloat16 hb = __float2bfloat16_rn(in[i]);
            hf[i] = __bfloat162float(hb);
            lf[i] = in[i] - hf[i];
        }
        uint4 hh = make_uint4(pack2(hf[0], hf[1]), pack2(hf[2], hf[3]),
                              pack2(hf[4], hf[5]), pack2(hf[6], hf[7]));
        uint4 ll = make_uint4(pack2(lf[0], lf[1]), pack2(lf[2], lf[3]),
                              pack2(lf[4], lf[5]), pack2(lf[6], lf[7]));
        *(uint4*)&Ah[row * PITCH + col8] = hh;
        *(uint4*)&Al[row * PITCH + col8] = ll;
    }
    // ---- B tiles: straight copy (already [NOUT][128] bf16) ----
    const __nv_bfloat16* wsrc[4] = {Wlh, Wll, Wrh, Wrl};
#pragma unroll
    for (int w = 0; w < 4; w++) {
        __nv_bfloat16* dst = Bt + w * (NOUT * PITCH);
        const __nv_bfloat16* src = wsrc[w];
        for (int c = tid; c < NOUT * 16; c += 256) {
            int row = c >> 4, col8 = (c & 15) << 3;
            *(uint4*)&dst[row * PITCH + col8] = *(const uint4*)&src[row * 128 + col8];
        }
    }
    __syncthreads();

    // ldmatrix per-lane address components
    const int quad = lane >> 3, r = lane & 7;
    const int a_row_off = (quad & 1) * 8 + r, a_col_off = (quad >> 1) * 8;   // A: x4 tiles
    const int b_row_off = (quad >> 1) * 8 + r, b_col_off = (quad & 1) * 8;   // B: n-pairs

    const uint32_t ah_u = smem_u32(Ah), al_u = smem_u32(Al), b_u = smem_u32(Bt);

#pragma unroll
    for (int out = 0; out < 2; out++) {
        float acc[2][NFRAG][4];
#pragma unroll
        for (int mf = 0; mf < 2; mf++)
#pragma unroll
            for (int nf = 0; nf < NFRAG; nf++)
                acc[mf][nf][0] = acc[mf][nf][1] = acc[mf][nf][2] = acc[mf][nf][3] = 0.f;

#pragma unroll
        for (int p = 0; p < 3; p++) {
            uint32_t a_base = (p == 2) ? al_u : ah_u;
            uint32_t b_base = b_u + (uint32_t)(out * 2 + (p == 1)) * BBYTES;
#pragma unroll
            for (int ks = 0; ks < 8; ks++) {
                uint32_t af[2][4];
#pragma unroll
                for (int mf = 0; mf < 2; mf++) {
                    uint32_t ad = a_base +
                        ((wm * 32 + mf * 16 + a_row_off) * PITCH + ks * 16 + a_col_off) * 2;
                    ldsm_x4(af[mf][0], af[mf][1], af[mf][2], af[mf][3], ad);
                }
                uint32_t bfr[NFRAG][2];
#pragma unroll
                for (int nfp = 0; nfp < NFRAG / 2; nfp++) {
                    uint32_t bd = b_base +
                        ((wn * WN + nfp * 16 + b_row_off) * PITCH + ks * 16 + b_col_off) * 2;
                    uint32_t d0, d1, d2, d3;
                    ldsm_x4(d0, d1, d2, d3, bd);
                    bfr[2 * nfp][0] = d0; bfr[2 * nfp][1] = d1;
                    bfr[2 * nfp + 1][0] = d2; bfr[2 * nfp + 1][1] = d3;
                }
#pragma unroll
                for (int mf = 0; mf < 2; mf++)
#pragma unroll
                    for (int nf = 0; nf < NFRAG; nf++)
                        mma16816(acc[mf][nf], af[mf], bfr[nf]);
            }
        }

        // ---- epilogue ----
        const float* bias = out ? br : bl;
        float* Y = out ? Yr : Yl;
#pragma unroll
        for (int mf = 0; mf < 2; mf++) {
            int row0 = base + wm * 32 + mf * 16 + (lane >> 2);
#pragma unroll
            for (int nf = 0; nf < NFRAG; nf++) {
                int col = wn * WN + nf * 8 + (lane & 3) * 2;
                float b0 = __ldg(&bias[col]), b1 = __ldg(&bias[col + 1]);
                if (row0 < nrows) {
                    float2 o = make_float2(acc[mf][nf][0] + b0, acc[mf][nf][1] + b1);
                    *(float2*)&Y[(size_t)row0 * NOUT + col] = o;
                }
                if (row0 + 8 < nrows) {
                    float2 o = make_float2(acc[mf][nf][2] + b0, acc[mf][nf][3] + b1);
                    *(float2*)&Y[(size_t)(row0 + 8) * NOUT + col] = o;
                }
            }
        }
    }
}

// ---------------- layer 1 fused attention ----------------
__global__ void k_attn1(const float* __restrict__ att, const float* __restrict__ bias, int N) {
    int node = blockIdx.x * 8 + (threadIdx.x >> 5);
    int lane = threadIdx.x & 31;
    if (node >= N) return;
    const int d = node;

    float4 xr = *(const float4*)&g_xr1[(size_t)d * 128 + lane * 4];
    float4 at = *(const float4*)&att[lane * 4];

    float4 self = *(const float4*)&g_xl1[(size_t)d * 128 + lane * 4];
    float sc = lrelu(self.x + xr.x) * at.x + lrelu(self.y + xr.y) * at.y +
               lrelu(self.z + xr.z) * at.z + lrelu(self.w + xr.w) * at.w;
    sc += __shfl_xor_sync(0xFFFFFFFFu, sc, 1);
    sc += __shfl_xor_sync(0xFFFFFFFFu, sc, 2);
    float m = sc, den = 1.f;
    float4 acc = self;

    const int beg = g_off[d], end = g_off[d + 1];
    float4 xl;
    if (beg < end) {
        int s0 = __ldg(&g_ssrc[beg]);
        xl = *(const float4*)&g_xl1[(size_t)s0 * 128 + lane * 4];
    }
    for (int j = beg; j < end; j++) {
        float4 cur = xl;
        if (j + 1 < end) {
            int sn = __ldg(&g_ssrc[j + 1]);
            xl = *(const float4*)&g_xl1[(size_t)sn * 128 + lane * 4];
        }
        sc = lrelu(cur.x + xr.x) * at.x + lrelu(cur.y + xr.y) * at.y +
             lrelu(cur.z + xr.z) * at.z + lrelu(cur.w + xr.w) * at.w;
        sc += __shfl_xor_sync(0xFFFFFFFFu, sc, 1);
        sc += __shfl_xor_sync(0xFFFFFFFFu, sc, 2);
        float nm = fmaxf(m, sc);
        float cold = __expf(m - nm), wgt = __expf(sc - nm);
        den = den * cold + wgt;
        acc.x = acc.x * cold + wgt * cur.x;
        acc.y = acc.y * cold + wgt * cur.y;
        acc.z = acc.z * cold + wgt * cur.z;
        acc.w = acc.w * cold + wgt * cur.w;
        m = nm;
    }
    float inv = 1.f / den;
    float4 bi = *(const float4*)&bias[lane * 4];
    float4 o;
    o.x = acc.x * inv + bi.x; o.y = acc.y * inv + bi.y;
    o.z = acc.z * inv + bi.z; o.w = acc.w * inv + bi.w;
    o.x = o.x > 0.f ? o.x : expm1f(o.x);
    o.y = o.y > 0.f ? o.y : expm1f(o.y);
    o.z = o.z > 0.f ? o.z : expm1f(o.z);
    o.w = o.w > 0.f ? o.w : expm1f(o.w);
    *(float4*)&g_h[(size_t)d * 128 + lane * 4] = o;
}

// ---------------- layer 2 fused attention ----------------
__global__ void k_attn2(const float* __restrict__ att2, const float* __restrict__ bias2,
                        float* __restrict__ dout, int N) {
    int node = blockIdx.x * 8 + (threadIdx.x >> 5);
    int lane = threadIdx.x & 31;
    if (node >= N) return;
    const int d = node;

    float xr0 = g_xr2[(size_t)d * 64 + lane];
    float xr1 = g_xr2[(size_t)d * 64 + lane + 32];
    float a0 = att2[lane], a1 = att2[lane + 32];

    float s0 = g_xl2[(size_t)d * 64 + lane];
    float s1 = g_xl2[(size_t)d * 64 + lane + 32];
    float sc = lrelu(s0 + xr0) * a0 + lrelu(s1 + xr1) * a1;
#pragma unroll
    for (int o = 16; o; o >>= 1) sc += __shfl_xor_sync(0xFFFFFFFFu, sc, o);
    float m = sc, den = 1.f;
    float acc0 = s0, acc1 = s1;

    const int beg = g_off[d], end = g_off[d + 1];
    float l0, l1;
    if (beg < end) {
        int sp = __ldg(&g_ssrc[beg]);
        l0 = g_xl2[(size_t)sp * 64 + lane];
        l1 = g_xl2[(size_t)sp * 64 + lane + 32];
    }
    for (int j = beg; j < end; j++) {
        float c0 = l0, c1 = l1;
        if (j + 1 < end) {
            int sn = __ldg(&g_ssrc[j + 1]);
            l0 = g_xl2[(size_t)sn * 64 + lane];
            l1 = g_xl2[(size_t)sn * 64 + lane + 32];
        }
        sc = lrelu(c0 + xr0) * a0 + lrelu(c1 + xr1) * a1;
#pragma unroll
        for (int o = 16; o; o >>= 1) sc += __shfl_xor_sync(0xFFFFFFFFu, sc, o);
        float nm = fmaxf(m, sc);
        float cold = __expf(m - nm), wgt = __expf(sc - nm);
        den = den * cold + wgt;
        acc0 = acc0 * cold + wgt * c0;
        acc1 = acc1 * cold + wgt * c1;
        m = nm;
    }
    float inv = 1.f / den;
    dout[(size_t)d * 64 + lane]      = acc0 * inv + bias2[lane];
    dout[(size_t)d * 64 + lane + 32] = acc1 * inv + bias2[lane + 32];
}

// ---------------- launch ----------------
static inline int cdiv(long long a, int b) { return (int)((a + b - 1) / b); }

extern "C" void kernel_launch(void* const* d_in, const int* in_sizes, int n_in,
                              void* d_out, int out_size) {
    const float* x    = (const float*)d_in[0];
    const int*   ei   = (const int*)d_in[1];
    const float* Wl1  = (const float*)d_in[2];
    const float* bl1  = (const float*)d_in[3];
    const float* Wr1  = (const float*)d_in[4];
    const float* br1  = (const float*)d_in[5];
    const float* att1 = (const float*)d_in[6];
    const float* bias1= (const float*)d_in[7];
    const float* Wl2  = (const float*)d_in[8];
    const float* bl2  = (const float*)d_in[9];
    const float* Wr2  = (const float*)d_in[10];
    const float* br2  = (const float*)d_in[11];
    const float* att2 = (const float*)d_in[12];
    const float* bias2= (const float*)d_in[13];
    float* dout = (float*)d_out;

    const int N = in_sizes[0] / 128;
    const int E = in_sizes[1] / 2;
    const int NB = cdiv(N, SCAN_B);

    float *xl1, *xr1, *h, *xl2, *xr2;
    cudaGetSymbolAddress((void**)&xl1, g_xl1);
    cudaGetSymbolAddress((void**)&xr1, g_xr1);
    cudaGetSymbolAddress((void**)&h,   g_h);
    cudaGetSymbolAddress((void**)&xl2, g_xl2);
    cudaGetSymbolAddress((void**)&xr2, g_xr2);
    __nv_bfloat16 *w1lh, *w1ll, *w1rh, *w1rl, *w2lh, *w2ll, *w2rh, *w2rl;
    cudaGetSymbolAddress((void**)&w1lh, g_w1lh);
    cudaGetSymbolAddress((void**)&w1ll, g_w1ll);
    cudaGetSymbolAddress((void**)&w1rh, g_w1rh);
    cudaGetSymbolAddress((void**)&w1rl, g_w1rl);
    cudaGetSymbolAddress((void**)&w2lh, g_w2lh);
    cudaGetSymbolAddress((void**)&w2ll, g_w2ll);
    cudaGetSymbolAddress((void**)&w2rh, g_w2rh);
    cudaGetSymbolAddress((void**)&w2rl, g_w2rl);

    // smem: 2 A tiles + 4 B tiles (padded pitch 136 halves)
    const int smem1 = 2 * 34816 + 4 * 34816;   // 208896 (NOUT=128)
    const int smem2 = 2 * 34816 + 4 * 17408;   // 139264 (NOUT=64)
    cudaFuncSetAttribute(k_gemm_mma<128>, cudaFuncAttributeMaxDynamicSharedMemorySize, smem1);
    cudaFuncSetAttribute(k_gemm_mma<64>,  cudaFuncAttributeMaxDynamicSharedMemorySize, smem2);

    // dtype + CSR build
    k_detect  <<<1, 256>>>(ei, E);
    k_zero_cnt<<<cdiv(N, 256), 256>>>(N);
    k_hist    <<<cdiv(E, 256), 256>>>(ei, E);
    k_scan1   <<<NB, SCAN_B>>>(N);
    k_scan2   <<<1, 128>>>(NB, N);
    k_scan3   <<<cdiv(N, 256), 256>>>(N);
    k_scatter <<<cdiv(E, 256), 256>>>(ei, E);

    // weight prep (bf16 split + transpose)
    k_wprep<<<cdiv(49152, 256), 256>>>(Wl1, Wr1, Wl2, Wr2);

    // layer 1
    k_gemm_mma<128><<<cdiv(N, 128), 256, smem1>>>(x, w1lh, w1ll, w1rh, w1rl,
                                                  bl1, br1, xl1, xr1, N);
    k_attn1<<<cdiv(N, 8), 256>>>(att1, bias1, N);

    // layer 2
    k_gemm_mma<64><<<cdiv(N, 128), 256, smem2>>>(h, w2lh, w2ll, w2rh, w2rl,
                                                 bl2, br2, xl2, xr2, N);
    k_attn2<<<cdiv(N, 8), 256>>>(att2, bias2, dout, N);
}